// round 1
// baseline (speedup 1.0000x reference)
#include <cuda_runtime.h>
#include <math.h>

#define NN    50000
#define FI    20
#define HIDD  500
#define NOUT  2
#define NPAIR 210            // upper-triangular (incl. diagonal) pairs of 20
#define BN_EPS 1e-5f

// ---- scratch (no allocations allowed; __device__ globals) ----
static __device__ int    g_deg[NN];
static __device__ float  g_dinv[NN];
static __device__ float4 g_aggX4[NN * 5];      // aggX: [NN, 20] fp32, 16B aligned
static __device__ double g_m[FI];              // column sums of aggX
static __device__ double g_G[NPAIR];           // upper-tri Gram aggX^T aggX
static __device__ float  g_M2[FI * NOUT];      // folded 20x2 head matrix
static __device__ float  g_C[NOUT];            // folded bias

// K1: reset per-call state (graph replays must be deterministic)
__global__ void k_init() {
    int t = blockIdx.x * blockDim.x + threadIdx.x;
    if (t < NN)    g_deg[t] = 1;               // self-loop contributes 1
    if (t < FI)    g_m[t] = 0.0;
    if (t < NPAIR) g_G[t] = 0.0;
}

// K2: in-degree histogram over col
__global__ void k_deg(const int* __restrict__ col, int E) {
    int t = blockIdx.x * blockDim.x + threadIdx.x;
    if (t < E) atomicAdd(&g_deg[col[t]], 1);
}

// K3: dinv = rsqrt(deg); init aggX with the self-loop term dinv[n]^2 * X[n]
__global__ void k_self(const float* __restrict__ X) {
    int n = blockIdx.x * blockDim.x + threadIdx.x;
    if (n >= NN) return;
    float d = rsqrtf((float)g_deg[n]);
    g_dinv[n] = d;
    float d2 = d * d;
    const float4* xr = (const float4*)(X + n * FI);
#pragma unroll
    for (int k = 0; k < 5; k++) {
        float4 v = xr[k];
        v.x *= d2; v.y *= d2; v.z *= d2; v.w *= d2;
        g_aggX4[n * 5 + k] = v;
    }
}

// K4: edge scatter in 20 dims: aggX[col] += dinv[row]*dinv[col] * X[row]
__global__ void k_scatter(const int* __restrict__ ei, const float* __restrict__ X, int E) {
    int e = blockIdx.x * blockDim.x + threadIdx.x;
    if (e >= E) return;
    int r = ei[e];
    int c = ei[E + e];
    float norm = g_dinv[r] * g_dinv[c];
    const float4* xr = (const float4*)(X + r * FI);
    float* a = (float*)(g_aggX4 + c * 5);
#pragma unroll
    for (int k = 0; k < 5; k++) {
        float4 v = xr[k];
        atomicAdd(a + 4 * k + 0, v.x * norm);
        atomicAdd(a + 4 * k + 1, v.y * norm);
        atomicAdd(a + 4 * k + 2, v.z * norm);
        atomicAdd(a + 4 * k + 3, v.w * norm);
    }
}

// K5: m = col-sums of aggX; G = upper-tri of aggX^T aggX (double accumulation)
__global__ void k_stats() {
    int t = threadIdx.x;                    // 256 threads; 230 active
    int i = 0, j = 0;
    bool isM = (t < FI);
    bool isG = (t >= FI) && (t < FI + NPAIR);
    if (isG) {
        int p = t - FI;
        while (p >= FI - i) { p -= FI - i; i++; }
        j = i + p;
    }
    double acc = 0.0;
    const float* base = (const float*)g_aggX4;
    for (int n = blockIdx.x; n < NN; n += gridDim.x) {
        const float* row = base + n * FI;
        if (isM)      acc += (double)row[t];
        else if (isG) acc += (double)row[i] * (double)row[j];
    }
    if (isM)      atomicAdd(&g_m[t], acc);
    else if (isG) atomicAdd(&g_G[t - FI], acc);
}

// K6 (1 block): fold BN into the head. Computes per-feature mean/var from (m, G),
// s/t scale-shift, the 20x2 folded matrix M2, bias C, and the rsu_embedding row.
__global__ void k_prep(const float* __restrict__ W,      // gcn_W  [20,500]
                       const float* __restrict__ b,      // gcn_b  [500]
                       const float* __restrict__ gamma,  // [500]
                       const float* __restrict__ beta,   // [500]
                       const float* __restrict__ W2,     // lin_W  [500,2]
                       const float* __restrict__ lb,     // lin_b  [2]
                       float* __restrict__ out_rsu) {    // d_out + NN*NOUT
    __shared__ float  sW[FI * HIDD];   // 40 KB
    __shared__ float  sS[HIDD], sT[HIDD];
    __shared__ double sm[FI];
    __shared__ double sG[NPAIR];
    int t = threadIdx.x;               // 512 threads
    for (int k = t; k < FI * HIDD; k += blockDim.x) sW[k] = W[k];
    if (t < FI)    sm[t] = g_m[t];
    if (t < NPAIR) sG[t] = g_G[t];
    __syncthreads();

    const float* a0 = (const float*)g_aggX4;   // node 0 row
    for (int f = t; f < HIDD; f += blockDim.x) {
        double bf = (double)b[f];
        double su = 0.0;
#pragma unroll
        for (int i2 = 0; i2 < FI; i2++) su += sm[i2] * (double)sW[i2 * HIDD + f];
        double mean = (su + (double)NN * bf) / (double)NN;
        double q = 0.0;
        int p = 0;
        for (int i2 = 0; i2 < FI; i2++) {
            double wi = (double)sW[i2 * HIDD + f];
            q += sG[p++] * wi * wi;
            for (int j2 = i2 + 1; j2 < FI; j2++)
                q += 2.0 * sG[p++] * wi * (double)sW[j2 * HIDD + f];
        }
        double sumsq = q + 2.0 * bf * su + (double)NN * bf * bf;
        double var = sumsq / (double)NN - mean * mean;
        float s  = gamma[f] * rsqrtf((float)var + BN_EPS);
        float tt = beta[f] - (float)mean * s;
        sS[f] = s; sT[f] = tt;
        // rsu_embedding (node 0): xn0 = (aggX0 . W_f + b_f)*s + t
        float u0 = 0.f;
#pragma unroll
        for (int i2 = 0; i2 < FI; i2++) u0 += a0[i2] * sW[i2 * HIDD + f];
        out_rsu[f] = (u0 + b[f]) * s + tt;
    }
    __syncthreads();

    if (t < FI * NOUT) {                  // M2[i][o] = sum_f W[i,f]*s_f*W2[f,o]
        int i2 = t / NOUT, o = t % NOUT;
        float acc = 0.f;
        for (int f = 0; f < HIDD; f++) acc += sW[i2 * HIDD + f] * sS[f] * W2[f * NOUT + o];
        g_M2[t] = acc;
    } else if (t < FI * NOUT + NOUT) {    // C[o] = sum_f (b_f*s_f + t_f)*W2[f,o] + lb[o]
        int o = t - FI * NOUT;
        float acc = lb[o];
        for (int f = 0; f < HIDD; f++) acc += (b[f] * sS[f] + sT[f]) * W2[f * NOUT + o];
        g_C[o] = acc;
    }
}

// K7: per-node head: logits = relu(aggX[n].M2 + C); softmax over 2 classes
__global__ void k_final(float* __restrict__ out) {
    __shared__ float sM[FI * NOUT];
    __shared__ float sC[NOUT];
    int t = threadIdx.x;
    if (t < FI * NOUT) sM[t] = g_M2[t];
    if (t < NOUT)      sC[t] = g_C[t];
    __syncthreads();
    int n = blockIdx.x * blockDim.x + t;
    if (n >= NN) return;
    float p0 = sC[0], p1 = sC[1];
    const float4* ar = (const float4*)(g_aggX4 + n * 5);
#pragma unroll
    for (int k = 0; k < 5; k++) {
        float4 v = ar[k];
        p0 += v.x * sM[(4 * k + 0) * NOUT] + v.y * sM[(4 * k + 1) * NOUT]
            + v.z * sM[(4 * k + 2) * NOUT] + v.w * sM[(4 * k + 3) * NOUT];
        p1 += v.x * sM[(4 * k + 0) * NOUT + 1] + v.y * sM[(4 * k + 1) * NOUT + 1]
            + v.z * sM[(4 * k + 2) * NOUT + 1] + v.w * sM[(4 * k + 3) * NOUT + 1];
    }
    float l0 = fmaxf(p0, 0.f), l1 = fmaxf(p1, 0.f);
    float mx = fmaxf(l0, l1);
    float e0 = expf(l0 - mx), e1 = expf(l1 - mx);
    float inv = 1.f / (e0 + e1);
    out[2 * n + 0] = e0 * inv;
    out[2 * n + 1] = e1 * inv;
}

extern "C" void kernel_launch(void* const* d_in, const int* in_sizes, int n_in,
                              void* d_out, int out_size) {
    const float* X     = (const float*)d_in[0];   // node_feature [50000,20]
    const int*   ei    = (const int*)  d_in[1];   // edge_index   [2,E]
    const float* gcnW  = (const float*)d_in[2];   // [20,500]
    const float* gcnB  = (const float*)d_in[3];   // [500]
    const float* gamma = (const float*)d_in[4];   // [500]
    const float* beta  = (const float*)d_in[5];   // [500]
    const float* linW  = (const float*)d_in[6];   // [500,2]
    const float* linB  = (const float*)d_in[7];   // [2]
    float* out = (float*)d_out;                   // [NN*2 action_prob][500 rsu]

    int E = in_sizes[1] / 2;

    int nb = (NN + 255) / 256;
    int eb = (E + 255) / 256;

    k_init<<<nb, 256>>>();
    k_deg<<<eb, 256>>>(ei + E, E);
    k_self<<<nb, 256>>>(X);
    k_scatter<<<eb, 256>>>(ei, X, E);
    k_stats<<<256, 256>>>();
    k_prep<<<1, 512>>>(gcnW, gcnB, gamma, beta, linW, linB, out + NN * NOUT);
    k_final<<<nb, 256>>>(out);
}

// round 2
// speedup vs baseline: 1.0990x; 1.0990x over previous
#include <cuda_runtime.h>
#include <math.h>

#define NN    50000
#define FI    20
#define HIDD  500
#define NOUT  2
#define NPAIR 210            // upper-triangular (incl. diag) pairs of 20
#define BN_EPS 1e-5f
#define CH    250            // rows per block in k_stats (200 blocks * 250 = 50000)

// ---- scratch (__device__ globals; no allocations allowed) ----
static __device__ int    g_deg[NN];
static __device__ float  g_dinv[NN];
static __device__ float4 g_Xs4[NN * 5];        // Xs = dinv[n] * X[n]
static __device__ float4 g_P4[NN * 5];         // P[c] = sum_{r->c} Xs[r]
static __device__ float4 g_agg4[NN * 5];       // aggX = dinv * (P + Xs)
static __device__ double g_m[FI];              // column sums of aggX
static __device__ double g_G[NPAIR];           // upper-tri Gram aggX^T aggX
static __device__ float  g_M2[FI * NOUT];      // folded 20x2 head matrix
static __device__ float  g_C[NOUT];            // folded bias

// K1: reset per-replay state (deterministic graph replays)
__global__ void k_init() {
    int t = blockIdx.x * blockDim.x + threadIdx.x;
    if (t < NN * 5) g_P4[t] = make_float4(0.f, 0.f, 0.f, 0.f);
    if (t < NN)     g_deg[t] = 1;              // self-loop contributes 1
    if (t < FI)     g_m[t] = 0.0;
    if (t < NPAIR)  g_G[t] = 0.0;
}

// K2: in-degree histogram over col
__global__ void k_deg(const int* __restrict__ col, int E) {
    int t = blockIdx.x * blockDim.x + threadIdx.x;
    if (t < E) atomicAdd(&g_deg[col[t]], 1);
}

// K3: dinv = rsqrt(deg); Xs[n] = dinv[n] * X[n]
__global__ void k_prepX(const float* __restrict__ X) {
    int n = blockIdx.x * blockDim.x + threadIdx.x;
    if (n >= NN) return;
    float d = rsqrtf((float)g_deg[n]);
    g_dinv[n] = d;
    const float4* xr = (const float4*)(X + n * FI);
#pragma unroll
    for (int k = 0; k < 5; k++) {
        float4 v = xr[k];
        v.x *= d; v.y *= d; v.z *= d; v.w *= d;
        g_Xs4[n * 5 + k] = v;
    }
}

// K4: edge scatter: P[c] += Xs[r]   (5x red.global.add.v4.f32 per edge)
__global__ void k_scatter(const int* __restrict__ ei, int E) {
    int e = blockIdx.x * blockDim.x + threadIdx.x;
    if (e >= E) return;
    int r = ei[e];
    int c = ei[E + e];
    const float4* __restrict__ src = g_Xs4 + r * 5;
    float4* dst = g_P4 + c * 5;
#pragma unroll
    for (int k = 0; k < 5; k++) {
        float4 v = __ldg(src + k);
        asm volatile("red.global.add.v4.f32 [%0], {%1, %2, %3, %4};"
                     :: "l"(dst + k), "f"(v.x), "f"(v.y), "f"(v.z), "f"(v.w)
                     : "memory");
    }
}

// K5: finalize aggX = dinv*(P+Xs) (coalesced, staged in shared) and
//     accumulate m (col sums) + G (upper-tri Gram) in double.
__global__ void k_stats() {
    __shared__ float s[CH * FI];               // 20 KB
    int t = threadIdx.x;                       // 256 threads
    int n0 = blockIdx.x * CH;

    // Phase A: finalize 250 rows (1250 float4 elements)
    for (int k = t; k < CH * 5; k += 256) {
        int row = k / 5;
        int n = n0 + row;
        float d = g_dinv[n];
        float4 p = g_P4[n * 5 + (k % 5)];
        float4 x = g_Xs4[n * 5 + (k % 5)];
        float4 a = make_float4(d * (p.x + x.x), d * (p.y + x.y),
                               d * (p.z + x.z), d * (p.w + x.w));
        g_agg4[n * 5 + (k % 5)] = a;
        ((float4*)s)[k] = a;
    }
    __syncthreads();

    // Phase B: 230 active threads: 20 for m, 210 for G pairs
    bool isM = (t < FI);
    bool isG = (t >= FI) && (t < FI + NPAIR);
    int i = 0, j = 0;
    if (isG) {
        int p = t - FI;
        while (p >= FI - i) { p -= FI - i; i++; }
        j = i + p;
    }
    double acc = 0.0;
    if (isM) {
        for (int n = 0; n < CH; n++) acc += (double)s[n * FI + t];
        atomicAdd(&g_m[t], acc);
    } else if (isG) {
        for (int n = 0; n < CH; n++)
            acc += (double)s[n * FI + i] * (double)s[n * FI + j];
        atomicAdd(&g_G[t - FI], acc);
    }
}

// K6 (1 block): fold BN into the head; emit rsu_embedding (node 0 row).
__global__ void k_prep(const float* __restrict__ W,      // gcn_W  [20,500]
                       const float* __restrict__ b,      // gcn_b  [500]
                       const float* __restrict__ gamma,  // [500]
                       const float* __restrict__ beta,   // [500]
                       const float* __restrict__ W2,     // lin_W  [500,2]
                       const float* __restrict__ lb,     // lin_b  [2]
                       float* __restrict__ out_rsu) {    // d_out + NN*NOUT
    __shared__ float  sW[FI * HIDD];   // 40 KB
    __shared__ float  sS[HIDD], sT[HIDD];
    __shared__ double sm[FI];
    __shared__ double sG[NPAIR];
    int t = threadIdx.x;               // 512 threads
    for (int k = t; k < FI * HIDD; k += blockDim.x) sW[k] = W[k];
    if (t < FI)    sm[t] = g_m[t];
    if (t < NPAIR) sG[t] = g_G[t];
    __syncthreads();

    const float* a0 = (const float*)g_agg4;   // node 0 row
    for (int f = t; f < HIDD; f += blockDim.x) {
        double bf = (double)b[f];
        double su = 0.0;
#pragma unroll
        for (int i2 = 0; i2 < FI; i2++) su += sm[i2] * (double)sW[i2 * HIDD + f];
        double mean = (su + (double)NN * bf) / (double)NN;
        double q = 0.0;
        int p = 0;
        for (int i2 = 0; i2 < FI; i2++) {
            double wi = (double)sW[i2 * HIDD + f];
            q += sG[p++] * wi * wi;
            for (int j2 = i2 + 1; j2 < FI; j2++)
                q += 2.0 * sG[p++] * wi * (double)sW[j2 * HIDD + f];
        }
        double sumsq = q + 2.0 * bf * su + (double)NN * bf * bf;
        double var = sumsq / (double)NN - mean * mean;
        float sc = gamma[f] * rsqrtf((float)var + BN_EPS);
        float tt = beta[f] - (float)mean * sc;
        sS[f] = sc; sT[f] = tt;
        float u0 = 0.f;
#pragma unroll
        for (int i2 = 0; i2 < FI; i2++) u0 += a0[i2] * sW[i2 * HIDD + f];
        out_rsu[f] = (u0 + b[f]) * sc + tt;
    }
    __syncthreads();

    if (t < FI * NOUT) {                  // M2[i][o] = sum_f W[i,f]*s_f*W2[f,o]
        int i2 = t / NOUT, o = t % NOUT;
        float acc = 0.f;
        for (int f = 0; f < HIDD; f++) acc += sW[i2 * HIDD + f] * sS[f] * W2[f * NOUT + o];
        g_M2[t] = acc;
    } else if (t < FI * NOUT + NOUT) {    // C[o] = sum_f (b_f*s_f + t_f)*W2[f,o] + lb[o]
        int o = t - FI * NOUT;
        float acc = lb[o];
        for (int f = 0; f < HIDD; f++) acc += (b[f] * sS[f] + sT[f]) * W2[f * NOUT + o];
        g_C[o] = acc;
    }
}

// K7: per-node head: logits = relu(aggX[n].M2 + C); softmax over 2 classes
__global__ void k_final(float* __restrict__ out) {
    __shared__ float sM[FI * NOUT];
    __shared__ float sC[NOUT];
    int t = threadIdx.x;
    if (t < FI * NOUT) sM[t] = g_M2[t];
    if (t < NOUT)      sC[t] = g_C[t];
    __syncthreads();
    int n = blockIdx.x * blockDim.x + t;
    if (n >= NN) return;
    float p0 = sC[0], p1 = sC[1];
    const float4* ar = (const float4*)(g_agg4 + n * 5);
#pragma unroll
    for (int k = 0; k < 5; k++) {
        float4 v = ar[k];
        p0 += v.x * sM[(4 * k + 0) * NOUT] + v.y * sM[(4 * k + 1) * NOUT]
            + v.z * sM[(4 * k + 2) * NOUT] + v.w * sM[(4 * k + 3) * NOUT];
        p1 += v.x * sM[(4 * k + 0) * NOUT + 1] + v.y * sM[(4 * k + 1) * NOUT + 1]
            + v.z * sM[(4 * k + 2) * NOUT + 1] + v.w * sM[(4 * k + 3) * NOUT + 1];
    }
    float l0 = fmaxf(p0, 0.f), l1 = fmaxf(p1, 0.f);
    float mx = fmaxf(l0, l1);
    float e0 = expf(l0 - mx), e1 = expf(l1 - mx);
    float inv = 1.f / (e0 + e1);
    out[2 * n + 0] = e0 * inv;
    out[2 * n + 1] = e1 * inv;
}

extern "C" void kernel_launch(void* const* d_in, const int* in_sizes, int n_in,
                              void* d_out, int out_size) {
    const float* X     = (const float*)d_in[0];   // node_feature [50000,20]
    const int*   ei    = (const int*)  d_in[1];   // edge_index   [2,E]
    const float* gcnW  = (const float*)d_in[2];   // [20,500]
    const float* gcnB  = (const float*)d_in[3];   // [500]
    const float* gamma = (const float*)d_in[4];   // [500]
    const float* beta  = (const float*)d_in[5];   // [500]
    const float* linW  = (const float*)d_in[6];   // [500,2]
    const float* linB  = (const float*)d_in[7];   // [2]
    float* out = (float*)d_out;                   // [NN*2 action_prob][500 rsu]

    int E = in_sizes[1] / 2;
    int nb  = (NN + 255) / 256;
    int nb5 = (NN * 5 + 255) / 256;
    int eb  = (E + 255) / 256;

    k_init<<<nb5, 256>>>();
    k_deg<<<eb, 256>>>(ei + E, E);
    k_prepX<<<nb, 256>>>(X);
    k_scatter<<<eb, 256>>>(ei, E);
    k_stats<<<NN / CH, 256>>>();
    k_prep<<<1, 512>>>(gcnW, gcnB, gamma, beta, linW, linB, out + NN * NOUT);
    k_final<<<nb, 256>>>(out);
}

// round 4
// speedup vs baseline: 4.1332x; 3.7609x over previous
#include <cuda_runtime.h>
#include <math.h>

#define NN    50000
#define FI    20
#define HIDD  500
#define NOUT  2
#define NPAIR 210            // upper-triangular (incl. diag) pairs of 20
#define BN_EPS 1e-5f
#define CH    250            // rows per block in k_stats (200 blocks)

// ---- scratch (__device__ globals; no allocations allowed) ----
static __device__ int    g_deg[NN];
static __device__ float  g_dinv[NN];
static __device__ float4 g_Xs4[NN * 5];        // Xs = dinv[n] * X[n]
static __device__ float4 g_P4[NN * 5];         // P[c] = sum_{r->c} Xs[r]
static __device__ float4 g_agg4[NN * 5];       // aggX = dinv * (P + Xs)
static __device__ double g_m[FI];              // column sums of aggX (combine in double)
static __device__ double g_G[NPAIR];           // upper-tri Gram (combine in double)
static __device__ float  g_M2[FI * NOUT];      // folded 20x2 head matrix
static __device__ float  g_C[NOUT];            // folded bias

// K1: reset per-replay state (deterministic graph replays)
__global__ void __launch_bounds__(256) k_init() {
    int t = blockIdx.x * blockDim.x + threadIdx.x;
    if (t < NN * 5) g_P4[t] = make_float4(0.f, 0.f, 0.f, 0.f);
    if (t < NN)     g_deg[t] = 1;              // self-loop contributes 1
    if (t < FI)     g_m[t] = 0.0;
    if (t < NPAIR)  g_G[t] = 0.0;
}

// K2: in-degree histogram over col
__global__ void __launch_bounds__(256) k_deg(const int* __restrict__ col, int E) {
    int t = blockIdx.x * blockDim.x + threadIdx.x;
    if (t < E) atomicAdd(&g_deg[col[t]], 1);
}

// K3: dinv = rsqrt(deg); Xs[n] = dinv[n] * X[n]
__global__ void __launch_bounds__(256) k_prepX(const float* __restrict__ X) {
    int n = blockIdx.x * blockDim.x + threadIdx.x;
    if (n >= NN) return;
    float d = rsqrtf((float)g_deg[n]);
    g_dinv[n] = d;
    const float4* xr = (const float4*)(X + n * FI);
#pragma unroll
    for (int k = 0; k < 5; k++) {
        float4 v = xr[k];
        v.x *= d; v.y *= d; v.z *= d; v.w *= d;
        g_Xs4[n * 5 + k] = v;
    }
}

// K4: edge scatter: P[c] += Xs[r]   (5x red.global.add.v4.f32 per edge)
__global__ void __launch_bounds__(256) k_scatter(const int* __restrict__ ei, int E) {
    int e = blockIdx.x * blockDim.x + threadIdx.x;
    if (e >= E) return;
    int r = ei[e];
    int c = ei[E + e];
    const float4* __restrict__ src = g_Xs4 + r * 5;
    float4* dst = g_P4 + c * 5;
#pragma unroll
    for (int k = 0; k < 5; k++) {
        float4 v = __ldg(src + k);
        asm volatile("red.global.add.v4.f32 [%0], {%1, %2, %3, %4};"
                     :: "l"(dst + k), "f"(v.x), "f"(v.y), "f"(v.z), "f"(v.w)
                     : "memory");
    }
}

// K5: finalize aggX = dinv*(P+Xs) (coalesced, staged in shared); accumulate
//     m (col sums) + G (Gram) in fp32 per block, combine in double (1 atomic).
__global__ void __launch_bounds__(256) k_stats() {
    __shared__ float s[CH * FI];               // 20 KB
    int t = threadIdx.x;                       // 256 threads
    int n0 = blockIdx.x * CH;

    // Phase A: finalize 250 rows (1250 float4 elements)
    for (int k = t; k < CH * 5; k += 256) {
        int n = n0 + k / 5;
        float d = g_dinv[n];
        float4 p = g_P4[n * 5 + (k % 5)];
        float4 x = g_Xs4[n * 5 + (k % 5)];
        float4 a = make_float4(d * (p.x + x.x), d * (p.y + x.y),
                               d * (p.z + x.z), d * (p.w + x.w));
        g_agg4[n * 5 + (k % 5)] = a;
        ((float4*)s)[k] = a;
    }
    __syncthreads();

    // Phase B: 230 active threads: 20 for m, 210 for G pairs (fp32 partials)
    bool isM = (t < FI);
    bool isG = (t >= FI) && (t < FI + NPAIR);
    int i = 0, j = 0;
    if (isG) {
        int p = t - FI;
        while (p >= FI - i) { p -= FI - i; i++; }
        j = i + p;
    }
    if (isM) {
        float a0 = 0.f, a1 = 0.f;
        for (int n = 0; n < CH; n += 2) {
            a0 += s[n * FI + t];
            a1 += s[(n + 1) * FI + t];
        }
        atomicAdd(&g_m[t], (double)(a0 + a1));
    } else if (isG) {
        float a0 = 0.f, a1 = 0.f;
        for (int n = 0; n < CH; n += 2) {
            a0 += s[n * FI + i] * s[n * FI + j];
            a1 += s[(n + 1) * FI + i] * s[(n + 1) * FI + j];
        }
        atomicAdd(&g_G[t - FI], (double)(a0 + a1));
    }
}

// K6 (1 block, 256 threads): fold BN into the head; emit rsu_embedding.
// Heavy loops in fp32; only the 20-term mean path stays double.
__global__ void __launch_bounds__(256) k_prep(
                       const float* __restrict__ W,      // gcn_W  [20,500]
                       const float* __restrict__ b,      // gcn_b  [500]
                       const float* __restrict__ gamma,  // [500]
                       const float* __restrict__ beta,   // [500]
                       const float* __restrict__ W2,     // lin_W  [500,2]
                       const float* __restrict__ lb,     // lin_b  [2]
                       float* __restrict__ out_rsu) {    // d_out + NN*NOUT
    __shared__ float  sW[FI * HIDD];   // 40 KB
    __shared__ float  sS[HIDD], sT[HIDD];
    __shared__ double sm[FI];
    __shared__ float  sGf[NPAIR];
    int t = threadIdx.x;               // 256 threads
    for (int k = t; k < FI * HIDD; k += blockDim.x) sW[k] = W[k];
    if (t < FI)    sm[t] = g_m[t];
    if (t < NPAIR) sGf[t] = (float)g_G[t];
    __syncthreads();

    const float* a0 = (const float*)g_agg4;   // node 0 row
    for (int f = t; f < HIDD; f += blockDim.x) {
        float bf = b[f];
        double su = 0.0;
#pragma unroll
        for (int i2 = 0; i2 < FI; i2++) su += sm[i2] * (double)sW[i2 * HIDD + f];
        float suf = (float)su;
        float mean = (suf + (float)NN * bf) * (1.f / (float)NN);
        // q = W_f^T G W_f over upper-tri pairs (fp32); outer unroll only
        float q = 0.f;
        int p = 0;
        for (int i2 = 0; i2 < FI; i2++) {
            float wi = sW[i2 * HIDD + f];
            q += sGf[p++] * wi * wi;
#pragma unroll 1
            for (int j2 = i2 + 1; j2 < FI; j2++)
                q += 2.f * sGf[p++] * wi * sW[j2 * HIDD + f];
        }
        float sumsq_over_n = q * (1.f / (float)NN) + 2.f * bf * suf * (1.f / (float)NN) + bf * bf;
        float var = sumsq_over_n - mean * mean;
        float sc = gamma[f] * rsqrtf(var + BN_EPS);
        float tt = beta[f] - mean * sc;
        sS[f] = sc; sT[f] = tt;
        float u0 = 0.f;
#pragma unroll
        for (int i2 = 0; i2 < FI; i2++) u0 += a0[i2] * sW[i2 * HIDD + f];
        out_rsu[f] = (u0 + bf) * sc + tt;
    }
    __syncthreads();

    if (t < FI * NOUT) {                  // M2[i][o] = sum_f W[i,f]*s_f*W2[f,o]
        int i2 = t / NOUT, o = t % NOUT;
        float acc = 0.f;
        for (int f = 0; f < HIDD; f++) acc += sW[i2 * HIDD + f] * sS[f] * W2[f * NOUT + o];
        g_M2[t] = acc;
    } else if (t < FI * NOUT + NOUT) {    // C[o] = sum_f (b_f*s_f + t_f)*W2[f,o] + lb[o]
        int o = t - FI * NOUT;
        float acc = lb[o];
        for (int f = 0; f < HIDD; f++) acc += (b[f] * sS[f] + sT[f]) * W2[f * NOUT + o];
        g_C[o] = acc;
    }
}

// K7: per-node head: logits = relu(aggX[n].M2 + C); softmax over 2 classes
__global__ void __launch_bounds__(256) k_final(float* __restrict__ out) {
    __shared__ float sM[FI * NOUT];
    __shared__ float sC[NOUT];
    int t = threadIdx.x;
    if (t < FI * NOUT) sM[t] = g_M2[t];
    if (t < NOUT)      sC[t] = g_C[t];
    __syncthreads();
    int n = blockIdx.x * blockDim.x + t;
    if (n >= NN) return;
    float p0 = sC[0], p1 = sC[1];
    const float4* ar = (const float4*)(g_agg4 + n * 5);
#pragma unroll
    for (int k = 0; k < 5; k++) {
        float4 v = ar[k];
        p0 += v.x * sM[(4 * k + 0) * NOUT] + v.y * sM[(4 * k + 1) * NOUT]
            + v.z * sM[(4 * k + 2) * NOUT] + v.w * sM[(4 * k + 3) * NOUT];
        p1 += v.x * sM[(4 * k + 0) * NOUT + 1] + v.y * sM[(4 * k + 1) * NOUT + 1]
            + v.z * sM[(4 * k + 2) * NOUT + 1] + v.w * sM[(4 * k + 3) * NOUT + 1];
    }
    float l0 = fmaxf(p0, 0.f), l1 = fmaxf(p1, 0.f);
    float mx = fmaxf(l0, l1);
    float e0 = expf(l0 - mx), e1 = expf(l1 - mx);
    float inv = 1.f / (e0 + e1);
    out[2 * n + 0] = e0 * inv;
    out[2 * n + 1] = e1 * inv;
}

extern "C" void kernel_launch(void* const* d_in, const int* in_sizes, int n_in,
                              void* d_out, int out_size) {
    const float* X     = (const float*)d_in[0];   // node_feature [50000,20]
    const int*   ei    = (const int*)  d_in[1];   // edge_index   [2,E]
    const float* gcnW  = (const float*)d_in[2];   // [20,500]
    const float* gcnB  = (const float*)d_in[3];   // [500]
    const float* gamma = (const float*)d_in[4];   // [500]
    const float* beta  = (const float*)d_in[5];   // [500]
    const float* linW  = (const float*)d_in[6];   // [500,2]
    const float* linB  = (const float*)d_in[7];   // [2]
    float* out = (float*)d_out;                   // [NN*2 action_prob][500 rsu]

    int E = in_sizes[1] / 2;
    int nb  = (NN + 255) / 256;
    int nb5 = (NN * 5 + 255) / 256;
    int eb  = (E + 255) / 256;

    k_init<<<nb5, 256>>>();
    k_deg<<<eb, 256>>>(ei + E, E);
    k_prepX<<<nb, 256>>>(X);
    k_scatter<<<eb, 256>>>(ei, E);
    k_stats<<<NN / CH, 256>>>();
    k_prep<<<1, 256>>>(gcnW, gcnB, gamma, beta, linW, linB, out + NN * NOUT);
    k_final<<<nb, 256>>>(out);
}

// round 5
// speedup vs baseline: 5.1962x; 1.2572x over previous
#include <cuda_runtime.h>
#include <math.h>

#define NN    50000
#define FI    20
#define HIDD  500
#define NOUT  2
#define NPAIR 210            // upper-triangular (incl. diag) pairs of 20
#define BN_EPS 1e-5f
#define CH    250            // rows per block in k_stats (200 blocks)

// ---- scratch (__device__ globals, zero-initialized; self-cleaning:
//      every kernel restores what it consumed to the zero state, so the
//      invariant "call starts from static-init state" holds on every replay.
static __device__ int    g_deg[NN];            // edge count (self-loop added in prepX)
static __device__ float  g_dinv[NN];
static __device__ float4 g_Xs4[NN * 5];        // Xs = dinv[n] * X[n]
static __device__ float4 g_P4[NN * 5];         // P[c] = sum_{r->c} Xs[r]
static __device__ float4 g_agg4[NN * 5];       // aggX = dinv * (P + Xs)
static __device__ double g_m[FI];              // column sums of aggX
static __device__ double g_G[NPAIR];           // upper-tri Gram aggX^T aggX
static __device__ float  g_M2[FI * NOUT];      // folded 20x2 head matrix
static __device__ float  g_C[NOUT];            // folded bias

// K1: in-degree histogram over col (g_deg starts at 0; int4 loads)
__global__ void __launch_bounds__(256) k_deg(const int* __restrict__ col, int E) {
    int t = blockIdx.x * blockDim.x + threadIdx.x;
    int e = 4 * t;
    if (e + 3 < E) {
        int4 c = *(const int4*)(col + e);
        atomicAdd(&g_deg[c.x], 1);
        atomicAdd(&g_deg[c.y], 1);
        atomicAdd(&g_deg[c.z], 1);
        atomicAdd(&g_deg[c.w], 1);
    } else {
        for (int k = e; k < E; k++) atomicAdd(&g_deg[col[k]], 1);
    }
}

// K2: dinv = rsqrt(cnt+1); Xs[n] = dinv[n] * X[n]; reset g_deg to 0
__global__ void __launch_bounds__(256) k_prepX(const float* __restrict__ X) {
    int n = blockIdx.x * blockDim.x + threadIdx.x;
    if (n >= NN) return;
    float d = rsqrtf((float)(g_deg[n] + 1));   // +1 = self loop
    g_deg[n] = 0;                              // self-clean for next replay
    g_dinv[n] = d;
    const float4* xr = (const float4*)(X + n * FI);
#pragma unroll
    for (int k = 0; k < 5; k++) {
        float4 v = xr[k];
        v.x *= d; v.y *= d; v.z *= d; v.w *= d;
        g_Xs4[n * 5 + k] = v;
    }
}

// K3: edge scatter: P[c] += Xs[r]   (5x red.global.add.v4.f32 per edge)
__global__ void __launch_bounds__(256) k_scatter(const int* __restrict__ ei, int E) {
    int e = blockIdx.x * blockDim.x + threadIdx.x;
    if (e >= E) return;
    int r = ei[e];
    int c = ei[E + e];
    const float4* __restrict__ src = g_Xs4 + r * 5;
    float4* dst = g_P4 + c * 5;
#pragma unroll
    for (int k = 0; k < 5; k++) {
        float4 v = __ldg(src + k);
        asm volatile("red.global.add.v4.f32 [%0], {%1, %2, %3, %4};"
                     :: "l"(dst + k), "f"(v.x), "f"(v.y), "f"(v.z), "f"(v.w)
                     : "memory");
    }
}

// K4: finalize aggX = dinv*(P+Xs); zero P4 (self-clean); accumulate
//     m (col sums) + G (Gram) in fp32 per block, combine via double atomics.
__global__ void __launch_bounds__(256) k_stats() {
    __shared__ float s[CH * FI];               // 20 KB
    int t = threadIdx.x;                       // 256 threads
    int n0 = blockIdx.x * CH;

    // Phase A: finalize 250 rows (1250 float4 elements)
    for (int k = t; k < CH * 5; k += 256) {
        int n = n0 + k / 5;
        int idx = n * 5 + (k % 5);
        float d = g_dinv[n];
        float4 p = g_P4[idx];
        float4 x = g_Xs4[idx];
        float4 a = make_float4(d * (p.x + x.x), d * (p.y + x.y),
                               d * (p.z + x.z), d * (p.w + x.w));
        g_agg4[idx] = a;
        g_P4[idx] = make_float4(0.f, 0.f, 0.f, 0.f);  // self-clean
        ((float4*)s)[k] = a;
    }
    __syncthreads();

    // Phase B: 230 active threads: 20 for m, 210 for G pairs (fp32 partials)
    bool isM = (t < FI);
    bool isG = (t >= FI) && (t < FI + NPAIR);
    int i = 0, j = 0;
    if (isG) {
        int p = t - FI;
        while (p >= FI - i) { p -= FI - i; i++; }
        j = i + p;
    }
    if (isM) {
        float a0 = 0.f, a1 = 0.f;
        for (int n = 0; n < CH; n += 2) {
            a0 += s[n * FI + t];
            a1 += s[(n + 1) * FI + t];
        }
        atomicAdd(&g_m[t], (double)(a0 + a1));
    } else if (isG) {
        float a0 = 0.f, a1 = 0.f;
        for (int n = 0; n < CH; n += 2) {
            a0 += s[n * FI + i] * s[n * FI + j];
            a1 += s[(n + 1) * FI + i] * s[(n + 1) * FI + j];
        }
        atomicAdd(&g_G[t - FI], (double)(a0 + a1));
    }
}

// K5 (1 block, 256 threads): fold BN into the head; emit rsu_embedding.
__global__ void __launch_bounds__(256) k_prep(
                       const float* __restrict__ W,      // gcn_W  [20,500]
                       const float* __restrict__ b,      // gcn_b  [500]
                       const float* __restrict__ gamma,  // [500]
                       const float* __restrict__ beta,   // [500]
                       const float* __restrict__ W2,     // lin_W  [500,2]
                       const float* __restrict__ lb,     // lin_b  [2]
                       float* __restrict__ out_rsu) {    // d_out + NN*NOUT
    __shared__ float  sW[FI * HIDD];   // 40 KB
    __shared__ float  sS[HIDD], sT[HIDD];
    __shared__ double sm[FI];
    __shared__ float  sGf[NPAIR];
    __shared__ float  sRed[42 * 6];
    int t = threadIdx.x;               // 256 threads
    for (int k = t; k < FI * HIDD; k += 256) sW[k] = W[k];
    if (t < FI)    { sm[t] = g_m[t];            g_m[t] = 0.0; }       // self-clean
    if (t < NPAIR) { sGf[t] = (float)g_G[t];    g_G[t] = 0.0; }       // self-clean
    __syncthreads();

    const float* a0 = (const float*)g_agg4;   // node 0 row
    for (int f = t; f < HIDD; f += 256) {
        float w[FI];
#pragma unroll
        for (int i2 = 0; i2 < FI; i2++) w[i2] = sW[i2 * HIDD + f];
        float bf = b[f];
        double su = 0.0;
#pragma unroll
        for (int i2 = 0; i2 < FI; i2++) su += sm[i2] * (double)w[i2];
        float suf = (float)su;
        float mean = (suf + (float)NN * bf) * (1.f / (float)NN);
        // q = W_f^T G W_f over upper-tri pairs (fully unrolled, registers)
        float q = 0.f;
        int p = 0;
#pragma unroll
        for (int i2 = 0; i2 < FI; i2++) {
            q += sGf[p++] * w[i2] * w[i2];
#pragma unroll
            for (int j2 = i2 + 1; j2 < FI; j2++)
                q += 2.f * sGf[p++] * w[i2] * w[j2];
        }
        float sumsq_over_n = q * (1.f / (float)NN)
                           + 2.f * bf * suf * (1.f / (float)NN) + bf * bf;
        float var = sumsq_over_n - mean * mean;
        float sc = gamma[f] * rsqrtf(var + BN_EPS);
        float tt = beta[f] - mean * sc;
        sS[f] = sc; sT[f] = tt;
        float u0 = 0.f;
#pragma unroll
        for (int i2 = 0; i2 < FI; i2++) u0 += a0[i2] * w[i2];
        out_rsu[f] = (u0 + bf) * sc + tt;
    }
    __syncthreads();

    // Parallel fold: 42 outputs (40 M2 entries + 2 C entries), 6 threads each.
    if (t < 42 * 6) {
        int o = t / 6, part = t % 6;
        int f0 = part * 84;
        int f1 = (f0 + 84 < HIDD) ? f0 + 84 : HIDD;
        float acc = 0.f;
        if (o < FI * NOUT) {                 // M2[i][oo] = sum_f W[i,f]*s_f*W2[f,oo]
            int i2 = o / NOUT, oo = o % NOUT;
            for (int f = f0; f < f1; f++)
                acc += sW[i2 * HIDD + f] * sS[f] * W2[f * NOUT + oo];
        } else {                             // C[oo] = sum_f (b_f*s_f + t_f)*W2[f,oo]
            int oo = o - FI * NOUT;
            for (int f = f0; f < f1; f++)
                acc += (b[f] * sS[f] + sT[f]) * W2[f * NOUT + oo];
        }
        sRed[t] = acc;
    }
    __syncthreads();
    if (t < 42) {
        float acc = 0.f;
#pragma unroll
        for (int k = 0; k < 6; k++) acc += sRed[t * 6 + k];
        if (t < FI * NOUT) g_M2[t] = acc;
        else               g_C[t - FI * NOUT] = acc + lb[t - FI * NOUT];
    }
}

// K6: per-node head: logits = relu(aggX[n].M2 + C); softmax over 2 classes
__global__ void __launch_bounds__(256) k_final(float* __restrict__ out) {
    __shared__ float sM[FI * NOUT];
    __shared__ float sC[NOUT];
    int t = threadIdx.x;
    if (t < FI * NOUT) sM[t] = g_M2[t];
    if (t < NOUT)      sC[t] = g_C[t];
    __syncthreads();
    int n = blockIdx.x * blockDim.x + t;
    if (n >= NN) return;
    float p0 = sC[0], p1 = sC[1];
    const float4* ar = (const float4*)(g_agg4 + n * 5);
#pragma unroll
    for (int k = 0; k < 5; k++) {
        float4 v = ar[k];
        p0 += v.x * sM[(4 * k + 0) * NOUT] + v.y * sM[(4 * k + 1) * NOUT]
            + v.z * sM[(4 * k + 2) * NOUT] + v.w * sM[(4 * k + 3) * NOUT];
        p1 += v.x * sM[(4 * k + 0) * NOUT + 1] + v.y * sM[(4 * k + 1) * NOUT + 1]
            + v.z * sM[(4 * k + 2) * NOUT + 1] + v.w * sM[(4 * k + 3) * NOUT + 1];
    }
    float l0 = fmaxf(p0, 0.f), l1 = fmaxf(p1, 0.f);
    float mx = fmaxf(l0, l1);
    float e0 = expf(l0 - mx), e1 = expf(l1 - mx);
    float inv = 1.f / (e0 + e1);
    out[2 * n + 0] = e0 * inv;
    out[2 * n + 1] = e1 * inv;
}

extern "C" void kernel_launch(void* const* d_in, const int* in_sizes, int n_in,
                              void* d_out, int out_size) {
    const float* X     = (const float*)d_in[0];   // node_feature [50000,20]
    const int*   ei    = (const int*)  d_in[1];   // edge_index   [2,E]
    const float* gcnW  = (const float*)d_in[2];   // [20,500]
    const float* gcnB  = (const float*)d_in[3];   // [500]
    const float* gamma = (const float*)d_in[4];   // [500]
    const float* beta  = (const float*)d_in[5];   // [500]
    const float* linW  = (const float*)d_in[6];   // [500,2]
    const float* linB  = (const float*)d_in[7];   // [2]
    float* out = (float*)d_out;                   // [NN*2 action_prob][500 rsu]

    int E = in_sizes[1] / 2;
    int nb  = (NN + 255) / 256;
    int eb  = (E + 255) / 256;
    int eb4 = (E / 4 + 255) / 256 + 1;

    k_deg<<<eb4, 256>>>(ei + E, E);
    k_prepX<<<nb, 256>>>(X);
    k_scatter<<<eb, 256>>>(ei, E);
    k_stats<<<NN / CH, 256>>>();
    k_prep<<<1, 256>>>(gcnW, gcnB, gamma, beta, linW, linB, out + NN * NOUT);
    k_final<<<nb, 256>>>(out);
}